// round 6
// baseline (speedup 1.0000x reference)
#include <cuda_runtime.h>
#include <cuda_fp16.h>
#include <math.h>

#define N_NODES 30000
#define E_EDGES 480000
#define VDIM    512
#define HID     32

#define SCAN_BLK 512
#define NBLKS ((N_NODES + SCAN_BLK - 1) / SCAN_BLK)   // 59

// fused kernel A block partition
#define VNORM_BLKS 3750   // 8 warps/block, warp per node
#define HIST_BLKS  256
#define BN_BLKS    118
// fused kernel B block partition
#define FILL_BLKS  512
#define MLP_BLKS   118

// ---- scratch (__device__ globals; no allocation allowed) ----
__device__ __half g_vh[N_NODES * VDIM];    // normalized visual, fp16 (30.7 MB)
__device__ float  g_p[N_NODES];            // p[n] = mlp(x)[n] . u
__device__ int    g_cnt[N_NODES];          // in-degree histogram
__device__ int    g_rowstart[N_NODES + 1]; // CSR row offsets (by dst)
__device__ int    g_cursor[N_NODES];       // fill cursors
__device__ int    g_csr[E_EDGES];          // src indices grouped by dst
__device__ int    g_bsum[NBLKS];
__device__ int    g_boff[NBLKS];
__device__ float  g_sum[HID];
__device__ float  g_sumsq[HID];
__device__ float  g_scale[HID];
__device__ float  g_shift[HID];
__device__ float  g_u[HID];
__device__ float  g_c;

// ---------------------------------------------------------------------------
__global__ void k_zero() {
    int i = blockIdx.x * blockDim.x + threadIdx.x;
    int stride = gridDim.x * blockDim.x;
    for (int j = i; j < N_NODES; j += stride) g_cnt[j] = 0;
    if (i < HID) { g_sum[i] = 0.f; g_sumsq[i] = 0.f; }
}

// ---------------------------------------------------------------------------
// K_A: fused  vnorm (blocks [0,3750)) | hist (blocks [3750,4006)) |
//             bnstats (blocks [4006,4124))
// ---------------------------------------------------------------------------
__global__ void k_A(const float* __restrict__ visual,
                    const int* __restrict__ ei,
                    const float* __restrict__ x,
                    const float* __restrict__ w1,
                    const float* __restrict__ b1) {
    int b = blockIdx.x;
    if (b < VNORM_BLKS) {
        // ---- vnorm: warp per node ----
        int gw   = (b * blockDim.x + threadIdx.x) >> 5;
        int lane = threadIdx.x & 31;
        if (gw >= N_NODES) return;
        const float4* v = (const float4*)(visual + (size_t)gw * VDIM);
        float4 f[4];
        float s = 0.f;
#pragma unroll
        for (int i = 0; i < 4; i++) {
            f[i] = v[i * 32 + lane];
            s = fmaf(f[i].x, f[i].x, s); s = fmaf(f[i].y, f[i].y, s);
            s = fmaf(f[i].z, f[i].z, s); s = fmaf(f[i].w, f[i].w, s);
        }
#pragma unroll
        for (int off = 16; off > 0; off >>= 1) s += __shfl_xor_sync(0xffffffffu, s, off);
        float rn = 1.0f / fmaxf(sqrtf(s), 1e-8f);
        __half2* out = (__half2*)(g_vh + (size_t)gw * VDIM);
#pragma unroll
        for (int i = 0; i < 4; i++) {
            __half2 h0 = __floats2half2_rn(f[i].x * rn, f[i].y * rn);
            __half2 h1 = __floats2half2_rn(f[i].z * rn, f[i].w * rn);
            uint2 pk;
            pk.x = *(unsigned int*)&h0;
            pk.y = *(unsigned int*)&h1;
            *(uint2*)(out + i * 64 + lane * 2) = pk;
        }
    } else if (b < VNORM_BLKS + HIST_BLKS) {
        // ---- hist: in-degree ----
        int i = (b - VNORM_BLKS) * blockDim.x + threadIdx.x;
        int stride = HIST_BLKS * blockDim.x;
        for (int e = i; e < E_EDGES; e += stride)
            atomicAdd(&g_cnt[ei[E_EDGES + e]], 1);
    } else {
        // ---- bnstats ----
        int n = (b - VNORM_BLKS - HIST_BLKS) * blockDim.x + threadIdx.x;
        int lane = threadIdx.x & 31;
        bool valid = (n < N_NODES);
        float x0 = 0.f, x1 = 0.f;
        if (valid) { x0 = x[2 * n]; x1 = x[2 * n + 1]; }
#pragma unroll
        for (int k = 0; k < HID; k++) {
            float h = valid ? fmaf(w1[2 * k], x0, fmaf(w1[2 * k + 1], x1, b1[k])) : 0.f;
            float s = h, s2 = h * h;
#pragma unroll
            for (int off = 16; off > 0; off >>= 1) {
                s  += __shfl_xor_sync(0xffffffffu, s,  off);
                s2 += __shfl_xor_sync(0xffffffffu, s2, off);
            }
            if (lane == 0) {
                atomicAdd(&g_sum[k], s);
                atomicAdd(&g_sumsq[k], s2);
            }
        }
    }
}

// ---------------------------------------------------------------------------
__global__ void k_prep(const float* __restrict__ gamma,
                       const float* __restrict__ beta,
                       const float* __restrict__ wc,
                       const float* __restrict__ bc,
                       const float* __restrict__ wp,
                       const float* __restrict__ bp) {
    int k = threadIdx.x;
    if (k >= HID) return;
    const float invN = 1.0f / (float)N_NODES;
    float mu  = g_sum[k] * invN;
    float var = g_sumsq[k] * invN - mu * mu;
    float rstd = rsqrtf(var + 1e-5f);
    float sc = rstd * gamma[k];
    g_scale[k] = sc;
    g_shift[k] = beta[k] - mu * sc;

    float u = 0.f;
#pragma unroll
    for (int j = 0; j < HID; j++) u = fmaf(wp[j], wc[j * HID + k], u);
    g_u[k] = u;

    if (k == 0) {
        float c = bp[0];
#pragma unroll
        for (int j = 0; j < HID; j++) c = fmaf(wp[j], bc[j], c);
        g_c = c;
    }
}

// ---------------------------------------------------------------------------
__global__ void k_scan1() {
    __shared__ int wsum[SCAN_BLK / 32];
    int b = blockIdx.x, tid = threadIdx.x, lane = tid & 31, wid = tid >> 5;
    int i = b * SCAN_BLK + tid;
    int v = (i < N_NODES) ? g_cnt[i] : 0;
    int xv = v;
#pragma unroll
    for (int off = 1; off < 32; off <<= 1) {
        int y = __shfl_up_sync(0xffffffffu, xv, off);
        if (lane >= off) xv += y;
    }
    if (lane == 31) wsum[wid] = xv;
    __syncthreads();
    if (tid == 0) {
        int run = 0;
#pragma unroll
        for (int k = 0; k < SCAN_BLK / 32; k++) { int t = wsum[k]; wsum[k] = run; run += t; }
        g_bsum[b] = run;
    }
    __syncthreads();
    if (i < N_NODES) g_rowstart[i] = xv - v + wsum[wid];
}

__global__ void k_scan2() {
    int lane = threadIdx.x;
    int v0 = (lane < NBLKS) ? g_bsum[lane] : 0;
    int v1 = (lane + 32 < NBLKS) ? g_bsum[lane + 32] : 0;
    int x0 = v0, x1 = v1;
#pragma unroll
    for (int off = 1; off < 32; off <<= 1) {
        int y = __shfl_up_sync(0xffffffffu, x0, off);
        if (lane >= off) x0 += y;
        int z = __shfl_up_sync(0xffffffffu, x1, off);
        if (lane >= off) x1 += z;
    }
    int tot0 = __shfl_sync(0xffffffffu, x0, 31);
    x1 += tot0;
    if (lane < NBLKS) g_boff[lane] = x0 - v0;
    if (lane + 32 < NBLKS) g_boff[lane + 32] = x1 - v1;
    if (lane == 0) g_rowstart[N_NODES] = E_EDGES;
}

__global__ void k_scan3() {
    int i = blockIdx.x * blockDim.x + threadIdx.x;
    if (i >= N_NODES) return;
    int r = g_rowstart[i] + g_boff[i / SCAN_BLK];
    g_rowstart[i] = r;
    g_cursor[i] = r;
}

// ---------------------------------------------------------------------------
// K_B: fused  fill (blocks [0,512)) | mlp (blocks [512,630))
// ---------------------------------------------------------------------------
__global__ void k_B(const int* __restrict__ ei,
                    const float* __restrict__ x,
                    const float* __restrict__ w1,
                    const float* __restrict__ b1,
                    const float* __restrict__ prelu_a,
                    const float* __restrict__ w2,
                    const float* __restrict__ b2) {
    __shared__ float swu[HID];
    __shared__ float ssc[HID], ssh[HID];
    __shared__ float sconst;
    int b = blockIdx.x;
    if (b < FILL_BLKS) {
        int i = b * blockDim.x + threadIdx.x;
        int stride = FILL_BLKS * blockDim.x;
        for (int e = i; e < E_EDGES; e += stride) {
            int dst = ei[E_EDGES + e];
            int pos = atomicAdd(&g_cursor[dst], 1);
            g_csr[pos] = ei[e];
        }
    } else {
        if (threadIdx.x < HID) {
            int k = threadIdx.x;
            float wu = 0.f;
#pragma unroll
            for (int j = 0; j < HID; j++) wu = fmaf(g_u[j], w2[j * HID + k], wu);
            swu[k] = wu;
            ssc[k] = g_scale[k];
            ssh[k] = g_shift[k];
            if (k == 0) {
                float c2 = 0.f;
#pragma unroll
                for (int j = 0; j < HID; j++) c2 = fmaf(g_u[j], b2[j], c2);
                sconst = c2;
            }
        }
        __syncthreads();

        int n = (b - FILL_BLKS) * blockDim.x + threadIdx.x;
        if (n >= N_NODES) return;
        float a = prelu_a[0];
        float x0 = x[2 * n], x1 = x[2 * n + 1];
        float p = sconst;
#pragma unroll
        for (int k = 0; k < HID; k++) {
            float h1 = fmaf(w1[2 * k], x0, fmaf(w1[2 * k + 1], x1, b1[k]));
            float h  = fmaf(h1, ssc[k], ssh[k]);
            float hp = (h >= 0.f) ? h : a * h;
            p = fmaf(hp, swu[k], p);
        }
        g_p[n] = p;
    }
}

// ---------------------------------------------------------------------------
// K_agg: 2 warps per dst node (each owns 256 of 512 dims).
//   Edge metadata gathered 32-wide; rows processed in chunks of 4 with
//   4 independent 16B loads in flight (software pipelined).
//   Pair reduction via shared memory (deterministic).
// ---------------------------------------------------------------------------
__global__ void k_agg(float* __restrict__ out) {
    __shared__ float spart[8];
    int wid  = threadIdx.x >> 5;
    int lane = threadIdx.x & 31;
    int node = blockIdx.x * 4 + (wid >> 1);
    int half = wid & 1;
    bool valid = (node < N_NODES);

    int beg = 0, end = 0;
    if (valid) { beg = g_rowstart[node]; end = g_rowstart[node + 1]; }

    const int roff = half * 32 + lane;   // uint4 index within row (64 per row)

    float acc[8];
#pragma unroll
    for (int j = 0; j < 8; j++) acc[j] = 0.f;

    for (int base = beg; base < end; base += 32) {
        int cnt = min(32, end - base);
        int   src = 0;
        float ps  = 0.f;
        if (lane < cnt) {
            src = __ldg(&g_csr[base + lane]);
            ps  = __ldg(&g_p[src]);
        }
        uint4 cur[4]; float pc[4];
        int c0 = min(4, cnt);
#pragma unroll
        for (int t = 0; t < 4; t++) {
            if (t < c0) {
                int s = __shfl_sync(0xffffffffu, src, t);
                pc[t] = __shfl_sync(0xffffffffu, ps, t);
                cur[t] = ((const uint4*)(g_vh + (size_t)s * VDIM))[roff];
            }
        }
        for (int j = 0; j < cnt; j += 4) {
            uint4 nx[4]; float pn[4];
            int rem = cnt - (j + 4); if (rem > 4) rem = 4;
#pragma unroll
            for (int t = 0; t < 4; t++) {
                if (t < rem) {
                    int s = __shfl_sync(0xffffffffu, src, j + 4 + t);
                    pn[t] = __shfl_sync(0xffffffffu, ps, j + 4 + t);
                    nx[t] = ((const uint4*)(g_vh + (size_t)s * VDIM))[roff];
                }
            }
            int m = cnt - j; if (m > 4) m = 4;
#pragma unroll
            for (int t = 0; t < 4; t++) {
                if (t < m) {
                    uint4 a = cur[t];
                    float p0 = pc[t];
                    float2 f;
                    f = __half22float2(*(__half2*)&a.x); acc[0] = fmaf(f.x, p0, acc[0]); acc[1] = fmaf(f.y, p0, acc[1]);
                    f = __half22float2(*(__half2*)&a.y); acc[2] = fmaf(f.x, p0, acc[2]); acc[3] = fmaf(f.y, p0, acc[3]);
                    f = __half22float2(*(__half2*)&a.z); acc[4] = fmaf(f.x, p0, acc[4]); acc[5] = fmaf(f.y, p0, acc[5]);
                    f = __half22float2(*(__half2*)&a.w); acc[6] = fmaf(f.x, p0, acc[6]); acc[7] = fmaf(f.y, p0, acc[7]);
                }
            }
#pragma unroll
            for (int t = 0; t < 4; t++) { cur[t] = nx[t]; pc[t] = pn[t]; }
        }
    }

    // dot accumulator with this half of vn_dst
    float s = 0.f;
    if (valid) {
        uint4 d = ((const uint4*)(g_vh + (size_t)node * VDIM))[roff];
        float2 f;
        f = __half22float2(*(__half2*)&d.x); s = fmaf(acc[0], f.x, s); s = fmaf(acc[1], f.y, s);
        f = __half22float2(*(__half2*)&d.y); s = fmaf(acc[2], f.x, s); s = fmaf(acc[3], f.y, s);
        f = __half22float2(*(__half2*)&d.z); s = fmaf(acc[4], f.x, s); s = fmaf(acc[5], f.y, s);
        f = __half22float2(*(__half2*)&d.w); s = fmaf(acc[6], f.x, s); s = fmaf(acc[7], f.y, s);
    }
#pragma unroll
    for (int off = 16; off > 0; off >>= 1) s += __shfl_xor_sync(0xffffffffu, s, off);

    if (lane == 0) spart[wid] = s;
    __syncthreads();
    if ((wid & 1) == 0 && lane == 0 && valid) {
        float tot = spart[wid] + spart[wid + 1];
        float deg = (float)(end - beg);
        out[node] = tot / fmaxf(deg, 1.0f) + g_c;
    }
}

// ---------------------------------------------------------------------------
extern "C" void kernel_launch(void* const* d_in, const int* in_sizes, int n_in,
                              void* d_out, int out_size) {
    const float* x       = (const float*)d_in[0];
    const float* visual  = (const float*)d_in[1];
    const int*   ei      = (const int*)d_in[2];
    const float* w1      = (const float*)d_in[3];
    const float* b1      = (const float*)d_in[4];
    const float* gamma   = (const float*)d_in[5];
    const float* beta    = (const float*)d_in[6];
    const float* prelu_a = (const float*)d_in[7];
    const float* w2      = (const float*)d_in[8];
    const float* b2      = (const float*)d_in[9];
    const float* wc      = (const float*)d_in[10];
    const float* bc      = (const float*)d_in[11];
    const float* wp      = (const float*)d_in[12];
    const float* bp      = (const float*)d_in[13];
    float*       out     = (float*)d_out;

    k_zero<<<128, 256>>>();
    k_A<<<VNORM_BLKS + HIST_BLKS + BN_BLKS, 256>>>(visual, ei, x, w1, b1);
    k_prep<<<1, 32>>>(gamma, beta, wc, bc, wp, bp);
    k_scan1<<<NBLKS, SCAN_BLK>>>();
    k_scan2<<<1, 32>>>();
    k_scan3<<<(N_NODES + 255) / 256, 256>>>();
    k_B<<<FILL_BLKS + MLP_BLKS, 256>>>(ei, x, w1, b1, prelu_a, w2, b2);
    k_agg<<<(N_NODES + 3) / 4, 256>>>(out);
}

// round 7
// speedup vs baseline: 1.4694x; 1.4694x over previous
#include <cuda_runtime.h>
#include <cuda_fp16.h>
#include <math.h>

#define N_NODES 30000
#define E_EDGES 480000
#define VDIM    512
#define HID     32

#define SCAN_BLK 512
#define NBLKS ((N_NODES + SCAN_BLK - 1) / SCAN_BLK)   // 59

// fused kernel A block partition
#define VNORM_BLKS 3750   // 8 warps/block, warp per node
#define HIST_BLKS  256
#define BN_BLKS    118
// fused kernel B block partition
#define FILL_BLKS  512
#define MLP_BLKS   118

// ---- scratch (__device__ globals; no allocation allowed) ----
__device__ __half g_vh[N_NODES * VDIM];    // normalized visual, fp16 (30.7 MB)
__device__ float  g_p[N_NODES];            // p[n] = mlp(x)[n] . u
__device__ int    g_cnt[N_NODES];          // in-degree histogram
__device__ int    g_rowstart[N_NODES + 1]; // CSR row offsets (by dst)
__device__ int    g_cursor[N_NODES];       // fill cursors
__device__ int    g_csr[E_EDGES];          // src indices grouped by dst
__device__ int    g_bsum[NBLKS];
__device__ int    g_boff[NBLKS];
__device__ float  g_sum[HID];
__device__ float  g_sumsq[HID];
__device__ float  g_scale[HID];
__device__ float  g_shift[HID];
__device__ float  g_u[HID];
__device__ float  g_c;

// ---------------------------------------------------------------------------
__global__ void k_zero() {
    int i = blockIdx.x * blockDim.x + threadIdx.x;
    int stride = gridDim.x * blockDim.x;
    for (int j = i; j < N_NODES; j += stride) g_cnt[j] = 0;
    if (i < HID) { g_sum[i] = 0.f; g_sumsq[i] = 0.f; }
}

// ---------------------------------------------------------------------------
// K_A: fused  vnorm (blocks [0,3750)) | hist | bnstats
// ---------------------------------------------------------------------------
__global__ void k_A(const float* __restrict__ visual,
                    const int* __restrict__ ei,
                    const float* __restrict__ x,
                    const float* __restrict__ w1,
                    const float* __restrict__ b1) {
    int b = blockIdx.x;
    if (b < VNORM_BLKS) {
        // ---- vnorm: warp per node ----
        int gw   = (b * blockDim.x + threadIdx.x) >> 5;
        int lane = threadIdx.x & 31;
        if (gw >= N_NODES) return;
        const float4* v = (const float4*)(visual + (size_t)gw * VDIM);
        float4 f[4];
        float s = 0.f;
#pragma unroll
        for (int i = 0; i < 4; i++) {
            f[i] = v[i * 32 + lane];
            s = fmaf(f[i].x, f[i].x, s); s = fmaf(f[i].y, f[i].y, s);
            s = fmaf(f[i].z, f[i].z, s); s = fmaf(f[i].w, f[i].w, s);
        }
#pragma unroll
        for (int off = 16; off > 0; off >>= 1) s += __shfl_xor_sync(0xffffffffu, s, off);
        float rn = 1.0f / fmaxf(sqrtf(s), 1e-8f);
        __half2* out = (__half2*)(g_vh + (size_t)gw * VDIM);
#pragma unroll
        for (int i = 0; i < 4; i++) {
            __half2 h0 = __floats2half2_rn(f[i].x * rn, f[i].y * rn);
            __half2 h1 = __floats2half2_rn(f[i].z * rn, f[i].w * rn);
            uint2 pk;
            pk.x = *(unsigned int*)&h0;
            pk.y = *(unsigned int*)&h1;
            *(uint2*)(out + i * 64 + lane * 2) = pk;
        }
    } else if (b < VNORM_BLKS + HIST_BLKS) {
        // ---- hist: in-degree ----
        int i = (b - VNORM_BLKS) * blockDim.x + threadIdx.x;
        int stride = HIST_BLKS * blockDim.x;
        for (int e = i; e < E_EDGES; e += stride)
            atomicAdd(&g_cnt[ei[E_EDGES + e]], 1);
    } else {
        // ---- bnstats ----
        int n = (b - VNORM_BLKS - HIST_BLKS) * blockDim.x + threadIdx.x;
        int lane = threadIdx.x & 31;
        bool valid = (n < N_NODES);
        float x0 = 0.f, x1 = 0.f;
        if (valid) { x0 = x[2 * n]; x1 = x[2 * n + 1]; }
#pragma unroll
        for (int k = 0; k < HID; k++) {
            float h = valid ? fmaf(w1[2 * k], x0, fmaf(w1[2 * k + 1], x1, b1[k])) : 0.f;
            float s = h, s2 = h * h;
#pragma unroll
            for (int off = 16; off > 0; off >>= 1) {
                s  += __shfl_xor_sync(0xffffffffu, s,  off);
                s2 += __shfl_xor_sync(0xffffffffu, s2, off);
            }
            if (lane == 0) {
                atomicAdd(&g_sum[k], s);
                atomicAdd(&g_sumsq[k], s2);
            }
        }
    }
}

// ---------------------------------------------------------------------------
__global__ void k_prep(const float* __restrict__ gamma,
                       const float* __restrict__ beta,
                       const float* __restrict__ wc,
                       const float* __restrict__ bc,
                       const float* __restrict__ wp,
                       const float* __restrict__ bp) {
    int k = threadIdx.x;
    if (k >= HID) return;
    const float invN = 1.0f / (float)N_NODES;
    float mu  = g_sum[k] * invN;
    float var = g_sumsq[k] * invN - mu * mu;
    float rstd = rsqrtf(var + 1e-5f);
    float sc = rstd * gamma[k];
    g_scale[k] = sc;
    g_shift[k] = beta[k] - mu * sc;

    float u = 0.f;
#pragma unroll
    for (int j = 0; j < HID; j++) u = fmaf(wp[j], wc[j * HID + k], u);
    g_u[k] = u;

    if (k == 0) {
        float c = bp[0];
#pragma unroll
        for (int j = 0; j < HID; j++) c = fmaf(wp[j], bc[j], c);
        g_c = c;
    }
}

// ---------------------------------------------------------------------------
__global__ void k_scan1() {
    __shared__ int wsum[SCAN_BLK / 32];
    int b = blockIdx.x, tid = threadIdx.x, lane = tid & 31, wid = tid >> 5;
    int i = b * SCAN_BLK + tid;
    int v = (i < N_NODES) ? g_cnt[i] : 0;
    int xv = v;
#pragma unroll
    for (int off = 1; off < 32; off <<= 1) {
        int y = __shfl_up_sync(0xffffffffu, xv, off);
        if (lane >= off) xv += y;
    }
    if (lane == 31) wsum[wid] = xv;
    __syncthreads();
    if (tid == 0) {
        int run = 0;
#pragma unroll
        for (int k = 0; k < SCAN_BLK / 32; k++) { int t = wsum[k]; wsum[k] = run; run += t; }
        g_bsum[b] = run;
    }
    __syncthreads();
    if (i < N_NODES) g_rowstart[i] = xv - v + wsum[wid];
}

__global__ void k_scan2() {
    int lane = threadIdx.x;
    int v0 = (lane < NBLKS) ? g_bsum[lane] : 0;
    int v1 = (lane + 32 < NBLKS) ? g_bsum[lane + 32] : 0;
    int x0 = v0, x1 = v1;
#pragma unroll
    for (int off = 1; off < 32; off <<= 1) {
        int y = __shfl_up_sync(0xffffffffu, x0, off);
        if (lane >= off) x0 += y;
        int z = __shfl_up_sync(0xffffffffu, x1, off);
        if (lane >= off) x1 += z;
    }
    int tot0 = __shfl_sync(0xffffffffu, x0, 31);
    x1 += tot0;
    if (lane < NBLKS) g_boff[lane] = x0 - v0;
    if (lane + 32 < NBLKS) g_boff[lane + 32] = x1 - v1;
    if (lane == 0) g_rowstart[N_NODES] = E_EDGES;
}

__global__ void k_scan3() {
    int i = blockIdx.x * blockDim.x + threadIdx.x;
    if (i >= N_NODES) return;
    int r = g_rowstart[i] + g_boff[i / SCAN_BLK];
    g_rowstart[i] = r;
    g_cursor[i] = r;
}

// ---------------------------------------------------------------------------
// K_B: fused  fill (blocks [0,512)) | mlp (blocks [512,630))
// ---------------------------------------------------------------------------
__global__ void k_B(const int* __restrict__ ei,
                    const float* __restrict__ x,
                    const float* __restrict__ w1,
                    const float* __restrict__ b1,
                    const float* __restrict__ prelu_a,
                    const float* __restrict__ w2,
                    const float* __restrict__ b2) {
    __shared__ float swu[HID];
    __shared__ float ssc[HID], ssh[HID];
    __shared__ float sconst;
    int b = blockIdx.x;
    if (b < FILL_BLKS) {
        int i = b * blockDim.x + threadIdx.x;
        int stride = FILL_BLKS * blockDim.x;
        for (int e = i; e < E_EDGES; e += stride) {
            int dst = ei[E_EDGES + e];
            int pos = atomicAdd(&g_cursor[dst], 1);
            g_csr[pos] = ei[e];
        }
    } else {
        if (threadIdx.x < HID) {
            int k = threadIdx.x;
            float wu = 0.f;
#pragma unroll
            for (int j = 0; j < HID; j++) wu = fmaf(g_u[j], w2[j * HID + k], wu);
            swu[k] = wu;
            ssc[k] = g_scale[k];
            ssh[k] = g_shift[k];
            if (k == 0) {
                float c2 = 0.f;
#pragma unroll
                for (int j = 0; j < HID; j++) c2 = fmaf(g_u[j], b2[j], c2);
                sconst = c2;
            }
        }
        __syncthreads();

        int n = (b - FILL_BLKS) * blockDim.x + threadIdx.x;
        if (n >= N_NODES) return;
        float a = prelu_a[0];
        float x0 = x[2 * n], x1 = x[2 * n + 1];
        float p = sconst;
#pragma unroll
        for (int k = 0; k < HID; k++) {
            float h1 = fmaf(w1[2 * k], x0, fmaf(w1[2 * k + 1], x1, b1[k]));
            float h  = fmaf(h1, ssc[k], ssh[k]);
            float hp = (h >= 0.f) ? h : a * h;
            p = fmaf(hp, swu[k], p);
        }
        g_p[n] = p;
    }
}

// ---------------------------------------------------------------------------
// K_agg (R5 version, known-good): warp per dst node, edge metadata gathered
// 32-wide, row loads software-pipelined 2 deep.
// ---------------------------------------------------------------------------
__global__ void k_agg(float* __restrict__ out) {
    int gw   = (blockIdx.x * blockDim.x + threadIdx.x) >> 5;
    int lane = threadIdx.x & 31;
    if (gw >= N_NODES) return;

    int beg = g_rowstart[gw];
    int end = g_rowstart[gw + 1];

    float acc[16];
#pragma unroll
    for (int j = 0; j < 16; j++) acc[j] = 0.f;

    for (int base = beg; base < end; base += 32) {
        int cnt = min(32, end - base);
        int   src = 0;
        float ps  = 0.f;
        if (lane < cnt) {
            src = __ldg(&g_csr[base + lane]);
            ps  = __ldg(&g_p[src]);
        }
        int   s0 = __shfl_sync(0xffffffffu, src, 0);
        float p0 = __shfl_sync(0xffffffffu, ps, 0);
        const uint4* r0 = (const uint4*)(g_vh + (size_t)s0 * VDIM);
        uint4 a0 = r0[lane];
        uint4 a1 = r0[32 + lane];

        for (int j = 0; j < cnt; j++) {
            uint4 b0, b1;
            float p1 = 0.f;
            if (j + 1 < cnt) {
                int s1 = __shfl_sync(0xffffffffu, src, j + 1);
                p1 = __shfl_sync(0xffffffffu, ps, j + 1);
                const uint4* rn = (const uint4*)(g_vh + (size_t)s1 * VDIM);
                b0 = rn[lane];
                b1 = rn[32 + lane];
            } else {
                b0 = a0; b1 = a1;
            }
            float2 f;
            f = __half22float2(*(__half2*)&a0.x); acc[0]  = fmaf(f.x, p0, acc[0]);  acc[1]  = fmaf(f.y, p0, acc[1]);
            f = __half22float2(*(__half2*)&a0.y); acc[2]  = fmaf(f.x, p0, acc[2]);  acc[3]  = fmaf(f.y, p0, acc[3]);
            f = __half22float2(*(__half2*)&a0.z); acc[4]  = fmaf(f.x, p0, acc[4]);  acc[5]  = fmaf(f.y, p0, acc[5]);
            f = __half22float2(*(__half2*)&a0.w); acc[6]  = fmaf(f.x, p0, acc[6]);  acc[7]  = fmaf(f.y, p0, acc[7]);
            f = __half22float2(*(__half2*)&a1.x); acc[8]  = fmaf(f.x, p0, acc[8]);  acc[9]  = fmaf(f.y, p0, acc[9]);
            f = __half22float2(*(__half2*)&a1.y); acc[10] = fmaf(f.x, p0, acc[10]); acc[11] = fmaf(f.y, p0, acc[11]);
            f = __half22float2(*(__half2*)&a1.z); acc[12] = fmaf(f.x, p0, acc[12]); acc[13] = fmaf(f.y, p0, acc[13]);
            f = __half22float2(*(__half2*)&a1.w); acc[14] = fmaf(f.x, p0, acc[14]); acc[15] = fmaf(f.y, p0, acc[15]);
            a0 = b0; a1 = b1; p0 = p1;
        }
    }

    // dot with vn_dst
    const uint4* b = (const uint4*)(g_vh + (size_t)gw * VDIM);
    uint4 d0 = b[lane];
    uint4 d1 = b[32 + lane];
    float s = 0.f;
    float2 f;
    f = __half22float2(*(__half2*)&d0.x); s = fmaf(acc[0],  f.x, s); s = fmaf(acc[1],  f.y, s);
    f = __half22float2(*(__half2*)&d0.y); s = fmaf(acc[2],  f.x, s); s = fmaf(acc[3],  f.y, s);
    f = __half22float2(*(__half2*)&d0.z); s = fmaf(acc[4],  f.x, s); s = fmaf(acc[5],  f.y, s);
    f = __half22float2(*(__half2*)&d0.w); s = fmaf(acc[6],  f.x, s); s = fmaf(acc[7],  f.y, s);
    f = __half22float2(*(__half2*)&d1.x); s = fmaf(acc[8],  f.x, s); s = fmaf(acc[9],  f.y, s);
    f = __half22float2(*(__half2*)&d1.y); s = fmaf(acc[10], f.x, s); s = fmaf(acc[11], f.y, s);
    f = __half22float2(*(__half2*)&d1.z); s = fmaf(acc[12], f.x, s); s = fmaf(acc[13], f.y, s);
    f = __half22float2(*(__half2*)&d1.w); s = fmaf(acc[14], f.x, s); s = fmaf(acc[15], f.y, s);

#pragma unroll
    for (int off = 16; off > 0; off >>= 1) s += __shfl_xor_sync(0xffffffffu, s, off);

    if (lane == 0) {
        float deg = (float)(end - beg);
        out[gw] = s / fmaxf(deg, 1.0f) + g_c;
    }
}

// ---------------------------------------------------------------------------
extern "C" void kernel_launch(void* const* d_in, const int* in_sizes, int n_in,
                              void* d_out, int out_size) {
    const float* x       = (const float*)d_in[0];
    const float* visual  = (const float*)d_in[1];
    const int*   ei      = (const int*)d_in[2];
    const float* w1      = (const float*)d_in[3];
    const float* b1      = (const float*)d_in[4];
    const float* gamma   = (const float*)d_in[5];
    const float* beta    = (const float*)d_in[6];
    const float* prelu_a = (const float*)d_in[7];
    const float* w2      = (const float*)d_in[8];
    const float* b2      = (const float*)d_in[9];
    const float* wc      = (const float*)d_in[10];
    const float* bc      = (const float*)d_in[11];
    const float* wp      = (const float*)d_in[12];
    const float* bp      = (const float*)d_in[13];
    float*       out     = (float*)d_out;

    k_zero<<<128, 256>>>();
    k_A<<<VNORM_BLKS + HIST_BLKS + BN_BLKS, 256>>>(visual, ei, x, w1, b1);
    k_prep<<<1, 32>>>(gamma, beta, wc, bc, wp, bp);
    k_scan1<<<NBLKS, SCAN_BLK>>>();
    k_scan2<<<1, 32>>>();
    k_scan3<<<(N_NODES + 255) / 256, 256>>>();
    k_B<<<FILL_BLKS + MLP_BLKS, 256>>>(ei, x, w1, b1, prelu_a, w2, b2);
    k_agg<<<(N_NODES * 32 + 255) / 256, 256>>>(out);
}

// round 8
// speedup vs baseline: 1.4905x; 1.0144x over previous
#include <cuda_runtime.h>
#include <cuda_fp16.h>
#include <math.h>

#define N_NODES 30000
#define E_EDGES 480000
#define VDIM    512
#define HID     32

#define SCAN_BLK 512
#define NBLKS ((N_NODES + SCAN_BLK - 1) / SCAN_BLK)   // 59

// k_A interleaved roles: groups of 11 blocks = 10 vnorm + 1 aux
#define KA_GRID  4125      // 375 groups
#define HIST_BLKS 256
#define BN_BLKS   118      // aux 256..373 ; aux 374 idle
// k_B partition
#define FILL_BLKS 512
#define MLP_BLKS  118

// ---- scratch (__device__ globals; no allocation allowed) ----
__device__ __half g_vh[N_NODES * VDIM];    // normalized visual, fp16 (30.7 MB)
__device__ float  g_p[N_NODES];
__device__ int    g_cnt[N_NODES];
__device__ int    g_rowstart[N_NODES + 1];
__device__ int    g_cursor[N_NODES];
__device__ int    g_csr[E_EDGES];
__device__ int    g_bsum[NBLKS];
__device__ int    g_arrive;
__device__ float  g_sum[HID];
__device__ float  g_sumsq[HID];
__device__ float  g_scale[HID];
__device__ float  g_shift[HID];
__device__ float  g_u[HID];
__device__ float  g_c;

// ---------------------------------------------------------------------------
__global__ void k_zero() {
    int i = blockIdx.x * blockDim.x + threadIdx.x;
    int stride = gridDim.x * blockDim.x;
    for (int j = i; j < N_NODES; j += stride) g_cnt[j] = 0;
    if (i < HID) { g_sum[i] = 0.f; g_sumsq[i] = 0.f; }
    if (i == HID) g_arrive = 0;
}

// ---------------------------------------------------------------------------
// K_A: interleaved  vnorm | hist | bnstats  (roles striped so all overlap)
// ---------------------------------------------------------------------------
__global__ void k_A(const float* __restrict__ visual,
                    const int* __restrict__ ei,
                    const float* __restrict__ x,
                    const float* __restrict__ w1,
                    const float* __restrict__ b1) {
    int b = blockIdx.x;
    int r = b % 11, q = b / 11;
    if (r < 10) {
        // ---- vnorm: warp per node ----
        int vb   = q * 10 + r;                 // 0..3749
        int gw   = (vb * blockDim.x + threadIdx.x) >> 5;
        int lane = threadIdx.x & 31;
        if (gw >= N_NODES) return;
        const float4* v = (const float4*)(visual + (size_t)gw * VDIM);
        float4 f[4];
        float s = 0.f;
#pragma unroll
        for (int i = 0; i < 4; i++) {
            f[i] = v[i * 32 + lane];
            s = fmaf(f[i].x, f[i].x, s); s = fmaf(f[i].y, f[i].y, s);
            s = fmaf(f[i].z, f[i].z, s); s = fmaf(f[i].w, f[i].w, s);
        }
#pragma unroll
        for (int off = 16; off > 0; off >>= 1) s += __shfl_xor_sync(0xffffffffu, s, off);
        float rn = 1.0f / fmaxf(sqrtf(s), 1e-8f);
        __half2* out = (__half2*)(g_vh + (size_t)gw * VDIM);
#pragma unroll
        for (int i = 0; i < 4; i++) {
            __half2 h0 = __floats2half2_rn(f[i].x * rn, f[i].y * rn);
            __half2 h1 = __floats2half2_rn(f[i].z * rn, f[i].w * rn);
            uint2 pk;
            pk.x = *(unsigned int*)&h0;
            pk.y = *(unsigned int*)&h1;
            *(uint2*)(out + i * 64 + lane * 2) = pk;
        }
    } else if (q < HIST_BLKS) {
        // ---- hist ----
        int i = q * blockDim.x + threadIdx.x;
        int stride = HIST_BLKS * blockDim.x;
        for (int e = i; e < E_EDGES; e += stride)
            atomicAdd(&g_cnt[ei[E_EDGES + e]], 1);
    } else if (q < HIST_BLKS + BN_BLKS) {
        // ---- bnstats ----
        int n = (q - HIST_BLKS) * blockDim.x + threadIdx.x;
        int lane = threadIdx.x & 31;
        bool valid = (n < N_NODES);
        float x0 = 0.f, x1 = 0.f;
        if (valid) { x0 = x[2 * n]; x1 = x[2 * n + 1]; }
#pragma unroll
        for (int k = 0; k < HID; k++) {
            float h = valid ? fmaf(w1[2 * k], x0, fmaf(w1[2 * k + 1], x1, b1[k])) : 0.f;
            float s = h, s2 = h * h;
#pragma unroll
            for (int off = 16; off > 0; off >>= 1) {
                s  += __shfl_xor_sync(0xffffffffu, s,  off);
                s2 += __shfl_xor_sync(0xffffffffu, s2, off);
            }
            if (lane == 0) {
                atomicAdd(&g_sum[k], s);
                atomicAdd(&g_sumsq[k], s2);
            }
        }
    }
}

// ---------------------------------------------------------------------------
// K_scanprep: blocks [0,59) do a grid-cooperative exclusive scan of g_cnt
// (all 60 blocks fit in one wave -> spin-wait is safe); block 59 does prep.
// ---------------------------------------------------------------------------
__global__ void k_scanprep(const float* __restrict__ gamma,
                           const float* __restrict__ beta,
                           const float* __restrict__ wc,
                           const float* __restrict__ bc,
                           const float* __restrict__ wp,
                           const float* __restrict__ bp) {
    int b = blockIdx.x;
    if (b == NBLKS) {
        // ---- prep (warp 0 only) ----
        int k = threadIdx.x;
        if (k >= HID) return;
        const float invN = 1.0f / (float)N_NODES;
        float mu  = g_sum[k] * invN;
        float var = g_sumsq[k] * invN - mu * mu;
        float rstd = rsqrtf(var + 1e-5f);
        float sc = rstd * gamma[k];
        g_scale[k] = sc;
        g_shift[k] = beta[k] - mu * sc;
        float u = 0.f;
#pragma unroll
        for (int j = 0; j < HID; j++) u = fmaf(wp[j], wc[j * HID + k], u);
        g_u[k] = u;
        if (k == 0) {
            float c = bp[0];
#pragma unroll
            for (int j = 0; j < HID; j++) c = fmaf(wp[j], bc[j], c);
            g_c = c;
        }
        return;
    }

    __shared__ int wsum[SCAN_BLK / 32 + 1];
    __shared__ int s_boff;
    int tid = threadIdx.x, lane = tid & 31, wid = tid >> 5;
    int i = b * SCAN_BLK + tid;
    int v = (i < N_NODES) ? g_cnt[i] : 0;
    int xv = v;
#pragma unroll
    for (int off = 1; off < 32; off <<= 1) {
        int y = __shfl_up_sync(0xffffffffu, xv, off);
        if (lane >= off) xv += y;
    }
    if (lane == 31) wsum[wid] = xv;
    __syncthreads();
    if (tid == 0) {
        int run = 0;
#pragma unroll
        for (int k = 0; k < SCAN_BLK / 32; k++) { int t = wsum[k]; wsum[k] = run; run += t; }
        g_bsum[b] = run;
        __threadfence();
        atomicAdd(&g_arrive, 1);
    }
    int local_excl = xv - v + ((tid == 0) ? 0 : 0); // placeholder, fixed below
    __syncthreads();
    local_excl = xv - v + wsum[wid];

    // wait for all 59 block sums
    if (tid == 0) {
        while (*(volatile int*)&g_arrive != NBLKS) { /* spin */ }
    }
    __syncthreads();
    __threadfence();

    // warp 0 computes this block's offset = sum of bsum[0..b-1]
    if (wid == 0) {
        int a0 = (lane < b) ? g_bsum[lane] : 0;
        int a1 = (lane + 32 < b) ? g_bsum[lane + 32] : 0;
        int t = a0 + a1;
#pragma unroll
        for (int off = 16; off > 0; off >>= 1) t += __shfl_xor_sync(0xffffffffu, t, off);
        if (lane == 0) s_boff = t;
    }
    __syncthreads();

    if (i < N_NODES) {
        int rr = local_excl + s_boff;
        g_rowstart[i] = rr;
        g_cursor[i] = rr;
    }
    if (b == NBLKS - 1 && tid == 0) g_rowstart[N_NODES] = E_EDGES;
}

// ---------------------------------------------------------------------------
// K_B: fused  fill (blocks [0,512)) | mlp (blocks [512,630))
// ---------------------------------------------------------------------------
__global__ void k_B(const int* __restrict__ ei,
                    const float* __restrict__ x,
                    const float* __restrict__ w1,
                    const float* __restrict__ b1,
                    const float* __restrict__ prelu_a,
                    const float* __restrict__ w2,
                    const float* __restrict__ b2) {
    __shared__ float swu[HID];
    __shared__ float ssc[HID], ssh[HID];
    __shared__ float sconst;
    int b = blockIdx.x;
    if (b < FILL_BLKS) {
        int i = b * blockDim.x + threadIdx.x;
        int stride = FILL_BLKS * blockDim.x;
        for (int e = i; e < E_EDGES; e += stride) {
            int dst = ei[E_EDGES + e];
            int pos = atomicAdd(&g_cursor[dst], 1);
            g_csr[pos] = ei[e];
        }
    } else {
        if (threadIdx.x < HID) {
            int k = threadIdx.x;
            float wu = 0.f;
#pragma unroll
            for (int j = 0; j < HID; j++) wu = fmaf(g_u[j], w2[j * HID + k], wu);
            swu[k] = wu;
            ssc[k] = g_scale[k];
            ssh[k] = g_shift[k];
            if (k == 0) {
                float c2 = 0.f;
#pragma unroll
                for (int j = 0; j < HID; j++) c2 = fmaf(g_u[j], b2[j], c2);
                sconst = c2;
            }
        }
        __syncthreads();

        int n = (b - FILL_BLKS) * blockDim.x + threadIdx.x;
        if (n >= N_NODES) return;
        float a = prelu_a[0];
        float x0 = x[2 * n], x1 = x[2 * n + 1];
        float p = sconst;
#pragma unroll
        for (int k = 0; k < HID; k++) {
            float h1 = fmaf(w1[2 * k], x0, fmaf(w1[2 * k + 1], x1, b1[k]));
            float h  = fmaf(h1, ssc[k], ssh[k]);
            float hp = (h >= 0.f) ? h : a * h;
            p = fmaf(hp, swu[k], p);
        }
        g_p[n] = p;
    }
}

// ---------------------------------------------------------------------------
// K_agg: warp per dst node; dst row preloaded before the edge loop;
// edge metadata gathered 32-wide; row loads software-pipelined 2 deep.
// ---------------------------------------------------------------------------
__global__ void k_agg(float* __restrict__ out) {
    int gw   = (blockIdx.x * blockDim.x + threadIdx.x) >> 5;
    int lane = threadIdx.x & 31;
    if (gw >= N_NODES) return;

    int beg = g_rowstart[gw];
    int end = g_rowstart[gw + 1];

    // preload dst row (independent of the edge loop — fills prologue latency)
    const uint4* bptr = (const uint4*)(g_vh + (size_t)gw * VDIM);
    uint4 d0 = __ldg(bptr + lane);
    uint4 d1 = __ldg(bptr + 32 + lane);

    float acc[16];
#pragma unroll
    for (int j = 0; j < 16; j++) acc[j] = 0.f;

    for (int base = beg; base < end; base += 32) {
        int cnt = min(32, end - base);
        int   src = 0;
        float ps  = 0.f;
        if (lane < cnt) {
            src = __ldg(&g_csr[base + lane]);
            ps  = __ldg(&g_p[src]);
        }
        int   s0 = __shfl_sync(0xffffffffu, src, 0);
        float p0 = __shfl_sync(0xffffffffu, ps, 0);
        const uint4* r0 = (const uint4*)(g_vh + (size_t)s0 * VDIM);
        uint4 a0 = r0[lane];
        uint4 a1 = r0[32 + lane];

        for (int j = 0; j < cnt; j++) {
            uint4 b0, b1;
            float p1 = 0.f;
            if (j + 1 < cnt) {
                int s1 = __shfl_sync(0xffffffffu, src, j + 1);
                p1 = __shfl_sync(0xffffffffu, ps, j + 1);
                const uint4* rn = (const uint4*)(g_vh + (size_t)s1 * VDIM);
                b0 = rn[lane];
                b1 = rn[32 + lane];
            } else {
                b0 = a0; b1 = a1;
            }
            float2 f;
            f = __half22float2(*(__half2*)&a0.x); acc[0]  = fmaf(f.x, p0, acc[0]);  acc[1]  = fmaf(f.y, p0, acc[1]);
            f = __half22float2(*(__half2*)&a0.y); acc[2]  = fmaf(f.x, p0, acc[2]);  acc[3]  = fmaf(f.y, p0, acc[3]);
            f = __half22float2(*(__half2*)&a0.z); acc[4]  = fmaf(f.x, p0, acc[4]);  acc[5]  = fmaf(f.y, p0, acc[5]);
            f = __half22float2(*(__half2*)&a0.w); acc[6]  = fmaf(f.x, p0, acc[6]);  acc[7]  = fmaf(f.y, p0, acc[7]);
            f = __half22float2(*(__half2*)&a1.x); acc[8]  = fmaf(f.x, p0, acc[8]);  acc[9]  = fmaf(f.y, p0, acc[9]);
            f = __half22float2(*(__half2*)&a1.y); acc[10] = fmaf(f.x, p0, acc[10]); acc[11] = fmaf(f.y, p0, acc[11]);
            f = __half22float2(*(__half2*)&a1.z); acc[12] = fmaf(f.x, p0, acc[12]); acc[13] = fmaf(f.y, p0, acc[13]);
            f = __half22float2(*(__half2*)&a1.w); acc[14] = fmaf(f.x, p0, acc[14]); acc[15] = fmaf(f.y, p0, acc[15]);
            a0 = b0; a1 = b1; p0 = p1;
        }
    }

    float s = 0.f;
    float2 f;
    f = __half22float2(*(__half2*)&d0.x); s = fmaf(acc[0],  f.x, s); s = fmaf(acc[1],  f.y, s);
    f = __half22float2(*(__half2*)&d0.y); s = fmaf(acc[2],  f.x, s); s = fmaf(acc[3],  f.y, s);
    f = __half22float2(*(__half2*)&d0.z); s = fmaf(acc[4],  f.x, s); s = fmaf(acc[5],  f.y, s);
    f = __half22float2(*(__half2*)&d0.w); s = fmaf(acc[6],  f.x, s); s = fmaf(acc[7],  f.y, s);
    f = __half22float2(*(__half2*)&d1.x); s = fmaf(acc[8],  f.x, s); s = fmaf(acc[9],  f.y, s);
    f = __half22float2(*(__half2*)&d1.y); s = fmaf(acc[10], f.x, s); s = fmaf(acc[11], f.y, s);
    f = __half22float2(*(__half2*)&d1.z); s = fmaf(acc[12], f.x, s); s = fmaf(acc[13], f.y, s);
    f = __half22float2(*(__half2*)&d1.w); s = fmaf(acc[14], f.x, s); s = fmaf(acc[15], f.y, s);

#pragma unroll
    for (int off = 16; off > 0; off >>= 1) s += __shfl_xor_sync(0xffffffffu, s, off);

    if (lane == 0) {
        float deg = (float)(end - beg);
        out[gw] = s / fmaxf(deg, 1.0f) + g_c;
    }
}

// ---------------------------------------------------------------------------
extern "C" void kernel_launch(void* const* d_in, const int* in_sizes, int n_in,
                              void* d_out, int out_size) {
    const float* x       = (const float*)d_in[0];
    const float* visual  = (const float*)d_in[1];
    const int*   ei      = (const int*)d_in[2];
    const float* w1      = (const float*)d_in[3];
    const float* b1      = (const float*)d_in[4];
    const float* gamma   = (const float*)d_in[5];
    const float* beta    = (const float*)d_in[6];
    const float* prelu_a = (const float*)d_in[7];
    const float* w2      = (const float*)d_in[8];
    const float* b2      = (const float*)d_in[9];
    const float* wc      = (const float*)d_in[10];
    const float* bc      = (const float*)d_in[11];
    const float* wp      = (const float*)d_in[12];
    const float* bp      = (const float*)d_in[13];
    float*       out     = (float*)d_out;

    k_zero<<<128, 256>>>();
    k_A<<<KA_GRID, 256>>>(visual, ei, x, w1, b1);
    k_scanprep<<<NBLKS + 1, SCAN_BLK>>>(gamma, beta, wc, bc, wp, bp);
    k_B<<<FILL_BLKS + MLP_BLKS, 256>>>(ei, x, w1, b1, prelu_a, w2, b2);
    k_agg<<<(N_NODES * 32 + 255) / 256, 256>>>(out);
}

// round 9
// speedup vs baseline: 1.5529x; 1.0419x over previous
#include <cuda_runtime.h>
#include <cuda_fp16.h>
#include <math.h>

#define N_NODES 30000
#define E_EDGES 480000
#define VDIM    512
#define HID     32

#define SCAN_BLK 512
#define NBLKS ((N_NODES + SCAN_BLK - 1) / SCAN_BLK)   // 59

// k_A interleaved roles: groups of 11 blocks = 10 vnorm + 1 aux
#define KA_GRID  4125      // 375 groups
#define HIST_BLKS 256
#define BN_BLKS   118
// k_B interleaved roles: groups of 17 = 16 fill + 1 mlp
#define FILL_BLKS 1875     // one edge per thread (1875*256 = 480000)
#define MLP_BLKS  118
#define KB_GRID   (118 * 17)   // 2006: fill blocks 0..1887 (13 idle), mlp 118

// ---- scratch (__device__ globals; no allocation allowed) ----
__device__ __half g_vh[N_NODES * VDIM];    // normalized visual, fp16 (30.7 MB)
__device__ float  g_p[N_NODES];
__device__ int    g_cnt[N_NODES];
__device__ int    g_rowstart[N_NODES + 1];
__device__ int    g_cursor[N_NODES];
__device__ int    g_csr[E_EDGES];
__device__ int    g_bsum[NBLKS];
__device__ int    g_arrive;
__device__ float  g_sum[HID];
__device__ float  g_sumsq[HID];
__device__ float  g_scale[HID];
__device__ float  g_shift[HID];
__device__ float  g_u[HID];
__device__ float  g_c;

// ---------------------------------------------------------------------------
__global__ void k_zero() {
    int i = blockIdx.x * blockDim.x + threadIdx.x;
    int stride = gridDim.x * blockDim.x;
    for (int j = i; j < N_NODES; j += stride) g_cnt[j] = 0;
    if (i < HID) { g_sum[i] = 0.f; g_sumsq[i] = 0.f; }
    if (i == HID) g_arrive = 0;
}

// ---------------------------------------------------------------------------
// K_A: interleaved  vnorm | hist | bnstats
// ---------------------------------------------------------------------------
__global__ void k_A(const float* __restrict__ visual,
                    const int* __restrict__ ei,
                    const float* __restrict__ x,
                    const float* __restrict__ w1,
                    const float* __restrict__ b1) {
    int b = blockIdx.x;
    int r = b % 11, q = b / 11;
    if (r < 10) {
        // ---- vnorm: warp per node ----
        int vb   = q * 10 + r;
        int gw   = (vb * blockDim.x + threadIdx.x) >> 5;
        int lane = threadIdx.x & 31;
        if (gw >= N_NODES) return;
        const float4* v = (const float4*)(visual + (size_t)gw * VDIM);
        float4 f[4];
        float s = 0.f;
#pragma unroll
        for (int i = 0; i < 4; i++) {
            f[i] = v[i * 32 + lane];
            s = fmaf(f[i].x, f[i].x, s); s = fmaf(f[i].y, f[i].y, s);
            s = fmaf(f[i].z, f[i].z, s); s = fmaf(f[i].w, f[i].w, s);
        }
#pragma unroll
        for (int off = 16; off > 0; off >>= 1) s += __shfl_xor_sync(0xffffffffu, s, off);
        float rn = 1.0f / fmaxf(sqrtf(s), 1e-8f);
        __half2* out = (__half2*)(g_vh + (size_t)gw * VDIM);
#pragma unroll
        for (int i = 0; i < 4; i++) {
            __half2 h0 = __floats2half2_rn(f[i].x * rn, f[i].y * rn);
            __half2 h1 = __floats2half2_rn(f[i].z * rn, f[i].w * rn);
            uint2 pk;
            pk.x = *(unsigned int*)&h0;
            pk.y = *(unsigned int*)&h1;
            *(uint2*)(out + i * 64 + lane * 2) = pk;
        }
    } else if (q < HIST_BLKS) {
        // ---- hist ----
        int i = q * blockDim.x + threadIdx.x;
        int stride = HIST_BLKS * blockDim.x;
        for (int e = i; e < E_EDGES; e += stride)
            atomicAdd(&g_cnt[ei[E_EDGES + e]], 1);
    } else if (q < HIST_BLKS + BN_BLKS) {
        // ---- bnstats ----
        int n = (q - HIST_BLKS) * blockDim.x + threadIdx.x;
        int lane = threadIdx.x & 31;
        bool valid = (n < N_NODES);
        float x0 = 0.f, x1 = 0.f;
        if (valid) { x0 = x[2 * n]; x1 = x[2 * n + 1]; }
#pragma unroll
        for (int k = 0; k < HID; k++) {
            float h = valid ? fmaf(w1[2 * k], x0, fmaf(w1[2 * k + 1], x1, b1[k])) : 0.f;
            float s = h, s2 = h * h;
#pragma unroll
            for (int off = 16; off > 0; off >>= 1) {
                s  += __shfl_xor_sync(0xffffffffu, s,  off);
                s2 += __shfl_xor_sync(0xffffffffu, s2, off);
            }
            if (lane == 0) {
                atomicAdd(&g_sum[k], s);
                atomicAdd(&g_sumsq[k], s2);
            }
        }
    }
}

// ---------------------------------------------------------------------------
// K_scanprep: blocks [0,59) grid-cooperative exclusive scan; block 59 = prep.
// ---------------------------------------------------------------------------
__global__ void k_scanprep(const float* __restrict__ gamma,
                           const float* __restrict__ beta,
                           const float* __restrict__ wc,
                           const float* __restrict__ bc,
                           const float* __restrict__ wp,
                           const float* __restrict__ bp) {
    int b = blockIdx.x;
    if (b == NBLKS) {
        int k = threadIdx.x;
        if (k >= HID) return;
        const float invN = 1.0f / (float)N_NODES;
        float mu  = g_sum[k] * invN;
        float var = g_sumsq[k] * invN - mu * mu;
        float rstd = rsqrtf(var + 1e-5f);
        float sc = rstd * gamma[k];
        g_scale[k] = sc;
        g_shift[k] = beta[k] - mu * sc;
        float u = 0.f;
#pragma unroll
        for (int j = 0; j < HID; j++) u = fmaf(wp[j], wc[j * HID + k], u);
        g_u[k] = u;
        if (k == 0) {
            float c = bp[0];
#pragma unroll
            for (int j = 0; j < HID; j++) c = fmaf(wp[j], bc[j], c);
            g_c = c;
        }
        return;
    }

    __shared__ int wsum[SCAN_BLK / 32 + 1];
    __shared__ int s_boff;
    int tid = threadIdx.x, lane = tid & 31, wid = tid >> 5;
    int i = b * SCAN_BLK + tid;
    int v = (i < N_NODES) ? g_cnt[i] : 0;
    int xv = v;
#pragma unroll
    for (int off = 1; off < 32; off <<= 1) {
        int y = __shfl_up_sync(0xffffffffu, xv, off);
        if (lane >= off) xv += y;
    }
    if (lane == 31) wsum[wid] = xv;
    __syncthreads();
    if (tid == 0) {
        int run = 0;
#pragma unroll
        for (int k = 0; k < SCAN_BLK / 32; k++) { int t = wsum[k]; wsum[k] = run; run += t; }
        g_bsum[b] = run;
        __threadfence();
        atomicAdd(&g_arrive, 1);
    }
    __syncthreads();
    int local_excl = xv - v + wsum[wid];

    if (tid == 0) {
        while (*(volatile int*)&g_arrive != NBLKS) { /* spin */ }
    }
    __syncthreads();
    __threadfence();

    if (wid == 0) {
        int a0 = (lane < b) ? g_bsum[lane] : 0;
        int a1 = (lane + 32 < b) ? g_bsum[lane + 32] : 0;
        int t = a0 + a1;
#pragma unroll
        for (int off = 16; off > 0; off >>= 1) t += __shfl_xor_sync(0xffffffffu, t, off);
        if (lane == 0) s_boff = t;
    }
    __syncthreads();

    if (i < N_NODES) {
        int rr = local_excl + s_boff;
        g_rowstart[i] = rr;
        g_cursor[i] = rr;
    }
    if (b == NBLKS - 1 && tid == 0) g_rowstart[N_NODES] = E_EDGES;
}

// ---------------------------------------------------------------------------
// K_B: interleaved  fill (one edge per thread) | mlp
// groups of 17 blocks = 16 fill + 1 mlp
// ---------------------------------------------------------------------------
__global__ void k_B(const int* __restrict__ ei,
                    const float* __restrict__ x,
                    const float* __restrict__ w1,
                    const float* __restrict__ b1,
                    const float* __restrict__ prelu_a,
                    const float* __restrict__ w2,
                    const float* __restrict__ b2) {
    __shared__ float swu[HID];
    __shared__ float ssc[HID], ssh[HID];
    __shared__ float sconst;
    int b = blockIdx.x;
    int r = b % 17, q = b / 17;
    if (r < 16) {
        int fb = q * 16 + r;
        if (fb >= FILL_BLKS) return;
        int e = fb * blockDim.x + threadIdx.x;   // exactly one edge per thread
        int dst = ei[E_EDGES + e];
        int src = ei[e];
        int pos = atomicAdd(&g_cursor[dst], 1);
        g_csr[pos] = src;
    } else {
        if (threadIdx.x < HID) {
            int k = threadIdx.x;
            float wu = 0.f;
#pragma unroll
            for (int j = 0; j < HID; j++) wu = fmaf(g_u[j], w2[j * HID + k], wu);
            swu[k] = wu;
            ssc[k] = g_scale[k];
            ssh[k] = g_shift[k];
            if (k == 0) {
                float c2 = 0.f;
#pragma unroll
                for (int j = 0; j < HID; j++) c2 = fmaf(g_u[j], b2[j], c2);
                sconst = c2;
            }
        }
        __syncthreads();

        int n = q * blockDim.x + threadIdx.x;
        if (n >= N_NODES) return;
        float a = prelu_a[0];
        float x0 = x[2 * n], x1 = x[2 * n + 1];
        float p = sconst;
#pragma unroll
        for (int k = 0; k < HID; k++) {
            float h1 = fmaf(w1[2 * k], x0, fmaf(w1[2 * k + 1], x1, b1[k]));
            float h  = fmaf(h1, ssc[k], ssh[k]);
            float hp = (h >= 0.f) ? h : a * h;
            p = fmaf(hp, swu[k], p);
        }
        g_p[n] = p;
    }
}

// ---------------------------------------------------------------------------
// K_agg: warp per dst node; dst row preloaded; metadata gathered 32-wide;
// row loads software-pipelined 2 deep.
// ---------------------------------------------------------------------------
__global__ void k_agg(float* __restrict__ out) {
    int gw   = (blockIdx.x * blockDim.x + threadIdx.x) >> 5;
    int lane = threadIdx.x & 31;
    if (gw >= N_NODES) return;

    int beg = g_rowstart[gw];
    int end = g_rowstart[gw + 1];

    const uint4* bptr = (const uint4*)(g_vh + (size_t)gw * VDIM);
    uint4 d0 = __ldg(bptr + lane);
    uint4 d1 = __ldg(bptr + 32 + lane);

    float acc[16];
#pragma unroll
    for (int j = 0; j < 16; j++) acc[j] = 0.f;

    for (int base = beg; base < end; base += 32) {
        int cnt = min(32, end - base);
        int   src = 0;
        float ps  = 0.f;
        if (lane < cnt) {
            src = __ldg(&g_csr[base + lane]);
            ps  = __ldg(&g_p[src]);
        }
        int   s0 = __shfl_sync(0xffffffffu, src, 0);
        float p0 = __shfl_sync(0xffffffffu, ps, 0);
        const uint4* r0 = (const uint4*)(g_vh + (size_t)s0 * VDIM);
        uint4 a0 = r0[lane];
        uint4 a1 = r0[32 + lane];

        for (int j = 0; j < cnt; j++) {
            uint4 b0, b1;
            float p1 = 0.f;
            if (j + 1 < cnt) {
                int s1 = __shfl_sync(0xffffffffu, src, j + 1);
                p1 = __shfl_sync(0xffffffffu, ps, j + 1);
                const uint4* rn = (const uint4*)(g_vh + (size_t)s1 * VDIM);
                b0 = rn[lane];
                b1 = rn[32 + lane];
            } else {
                b0 = a0; b1 = a1;
            }
            float2 f;
            f = __half22float2(*(__half2*)&a0.x); acc[0]  = fmaf(f.x, p0, acc[0]);  acc[1]  = fmaf(f.y, p0, acc[1]);
            f = __half22float2(*(__half2*)&a0.y); acc[2]  = fmaf(f.x, p0, acc[2]);  acc[3]  = fmaf(f.y, p0, acc[3]);
            f = __half22float2(*(__half2*)&a0.z); acc[4]  = fmaf(f.x, p0, acc[4]);  acc[5]  = fmaf(f.y, p0, acc[5]);
            f = __half22float2(*(__half2*)&a0.w); acc[6]  = fmaf(f.x, p0, acc[6]);  acc[7]  = fmaf(f.y, p0, acc[7]);
            f = __half22float2(*(__half2*)&a1.x); acc[8]  = fmaf(f.x, p0, acc[8]);  acc[9]  = fmaf(f.y, p0, acc[9]);
            f = __half22float2(*(__half2*)&a1.y); acc[10] = fmaf(f.x, p0, acc[10]); acc[11] = fmaf(f.y, p0, acc[11]);
            f = __half22float2(*(__half2*)&a1.z); acc[12] = fmaf(f.x, p0, acc[12]); acc[13] = fmaf(f.y, p0, acc[13]);
            f = __half22float2(*(__half2*)&a1.w); acc[14] = fmaf(f.x, p0, acc[14]); acc[15] = fmaf(f.y, p0, acc[15]);
            a0 = b0; a1 = b1; p0 = p1;
        }
    }

    float s = 0.f;
    float2 f;
    f = __half22float2(*(__half2*)&d0.x); s = fmaf(acc[0],  f.x, s); s = fmaf(acc[1],  f.y, s);
    f = __half22float2(*(__half2*)&d0.y); s = fmaf(acc[2],  f.x, s); s = fmaf(acc[3],  f.y, s);
    f = __half22float2(*(__half2*)&d0.z); s = fmaf(acc[4],  f.x, s); s = fmaf(acc[5],  f.y, s);
    f = __half22float2(*(__half2*)&d0.w); s = fmaf(acc[6],  f.x, s); s = fmaf(acc[7],  f.y, s);
    f = __half22float2(*(__half2*)&d1.x); s = fmaf(acc[8],  f.x, s); s = fmaf(acc[9],  f.y, s);
    f = __half22float2(*(__half2*)&d1.y); s = fmaf(acc[10], f.x, s); s = fmaf(acc[11], f.y, s);
    f = __half22float2(*(__half2*)&d1.z); s = fmaf(acc[12], f.x, s); s = fmaf(acc[13], f.y, s);
    f = __half22float2(*(__half2*)&d1.w); s = fmaf(acc[14], f.x, s); s = fmaf(acc[15], f.y, s);

#pragma unroll
    for (int off = 16; off > 0; off >>= 1) s += __shfl_xor_sync(0xffffffffu, s, off);

    if (lane == 0) {
        float deg = (float)(end - beg);
        out[gw] = s / fmaxf(deg, 1.0f) + g_c;
    }
}

// ---------------------------------------------------------------------------
extern "C" void kernel_launch(void* const* d_in, const int* in_sizes, int n_in,
                              void* d_out, int out_size) {
    const float* x       = (const float*)d_in[0];
    const float* visual  = (const float*)d_in[1];
    const int*   ei      = (const int*)d_in[2];
    const float* w1      = (const float*)d_in[3];
    const float* b1      = (const float*)d_in[4];
    const float* gamma   = (const float*)d_in[5];
    const float* beta    = (const float*)d_in[6];
    const float* prelu_a = (const float*)d_in[7];
    const float* w2      = (const float*)d_in[8];
    const float* b2      = (const float*)d_in[9];
    const float* wc      = (const float*)d_in[10];
    const float* bc      = (const float*)d_in[11];
    const float* wp      = (const float*)d_in[12];
    const float* bp      = (const float*)d_in[13];
    float*       out     = (float*)d_out;

    k_zero<<<128, 256>>>();
    k_A<<<KA_GRID, 256>>>(visual, ei, x, w1, b1);
    k_scanprep<<<NBLKS + 1, SCAN_BLK>>>(gamma, beta, wc, bc, wp, bp);
    k_B<<<KB_GRID, 256>>>(ei, x, w1, b1, prelu_a, w2, b2);
    k_agg<<<(N_NODES * 32 + 255) / 256, 256>>>(out);
}